// round 1
// baseline (speedup 1.0000x reference)
#include <cuda_runtime.h>
#include <math.h>

#define B_   4
#define T_   1024
#define DIM_ 2048
#define NH   32
#define NKV  8
#define HD   64

// Scratch (allocation-free rule: __device__ globals)
__device__ float g_q[(size_t)B_ * T_ * NH * HD];   // 32 MB
__device__ float g_k[(size_t)B_ * T_ * NKV * HD];  // 8 MB
__device__ float g_v[(size_t)B_ * T_ * NKV * HD];  // 8 MB
__device__ float g_o[(size_t)B_ * T_ * NH * HD];   // 32 MB

// ---------------------------------------------------------------------------
// SGEMM: C[M,N] = A[M,K] * B[N,K]^T   (A,B,C row-major, all dims multiples of tile)
// 128x128 block tile, BK=16, 256 threads, 8x8 per-thread micro tile.
// ---------------------------------------------------------------------------
#define BM 128
#define BN 128
#define BK 16

__global__ __launch_bounds__(256) void sgemm_nt(
    const float* __restrict__ A, const float* __restrict__ Bm,
    float* __restrict__ C, int M, int N, int K)
{
    __shared__ __align__(16) float As[BK][BM + 4];
    __shared__ __align__(16) float Bs[BK][BN + 4];

    const int tid = threadIdx.x;
    const int m0 = blockIdx.y * BM;
    const int n0 = blockIdx.x * BN;
    const int ty = tid >> 4;        // 0..15
    const int tx = tid & 15;        // 0..15

    float acc[8][8];
#pragma unroll
    for (int i = 0; i < 8; i++)
#pragma unroll
        for (int j = 0; j < 8; j++) acc[i][j] = 0.0f;

    const int lr = tid >> 2;        // 0..63
    const int lc = (tid & 3) * 4;   // 0,4,8,12

    for (int k0 = 0; k0 < K; k0 += BK) {
#pragma unroll
        for (int h = 0; h < 2; h++) {
            int row = lr + h * 64;
            float4 a4 = *(const float4*)(A + (size_t)(m0 + row) * K + k0 + lc);
            As[lc + 0][row] = a4.x; As[lc + 1][row] = a4.y;
            As[lc + 2][row] = a4.z; As[lc + 3][row] = a4.w;
            float4 b4 = *(const float4*)(Bm + (size_t)(n0 + row) * K + k0 + lc);
            Bs[lc + 0][row] = b4.x; Bs[lc + 1][row] = b4.y;
            Bs[lc + 2][row] = b4.z; Bs[lc + 3][row] = b4.w;
        }
        __syncthreads();

#pragma unroll
        for (int kk = 0; kk < BK; kk++) {
            float a[8], b[8];
            *(float4*)(a)     = *(const float4*)(&As[kk][ty * 8]);
            *(float4*)(a + 4) = *(const float4*)(&As[kk][ty * 8 + 4]);
            *(float4*)(b)     = *(const float4*)(&Bs[kk][tx * 8]);
            *(float4*)(b + 4) = *(const float4*)(&Bs[kk][tx * 8 + 4]);
#pragma unroll
            for (int i = 0; i < 8; i++)
#pragma unroll
                for (int j = 0; j < 8; j++)
                    acc[i][j] = fmaf(a[i], b[j], acc[i][j]);
        }
        __syncthreads();
    }

#pragma unroll
    for (int i = 0; i < 8; i++) {
        float* crow = C + (size_t)(m0 + ty * 8 + i) * N + n0 + tx * 8;
        float4 r0 = make_float4(acc[i][0], acc[i][1], acc[i][2], acc[i][3]);
        float4 r1 = make_float4(acc[i][4], acc[i][5], acc[i][6], acc[i][7]);
        *(float4*)(crow)     = r0;
        *(float4*)(crow + 4) = r1;
    }
}

// ---------------------------------------------------------------------------
// RoPE (interleaved pairs), in place. buf layout [B*T, nheads, 64].
// ---------------------------------------------------------------------------
__global__ void rope_kernel(float* __restrict__ buf,
                            const float* __restrict__ cosb,
                            const float* __restrict__ sinb,
                            int nheads)
{
    int idx = blockIdx.x * blockDim.x + threadIdx.x;
    int total = B_ * T_ * nheads * (HD / 2);
    if (idx >= total) return;
    int p  = idx & 31;
    int h  = (idx >> 5) % nheads;
    int bt = idx / (32 * nheads);
    int t  = bt % T_;
    size_t base = ((size_t)bt * nheads + h) * HD + 2 * p;
    float e = buf[base], o = buf[base + 1];
    float c = cosb[t * 32 + p], s = sinb[t * 32 + p];
    buf[base]     = e * c - o * s;
    buf[base + 1] = e * s + o * c;
}

// ---------------------------------------------------------------------------
// Causal GQA flash attention, fp32.
// Grid: (T/64, B*NH). 256 threads. Q tile 64, KV tile 64.
// Thread (rg=tid/16, kg=tid%16) owns rows rg*4..+4, keys/dims kg*4..+4.
// ---------------------------------------------------------------------------
#define NEG_BIG (-1e30f)

__global__ __launch_bounds__(256) void attn_kernel()
{
    const int qb = blockIdx.x;
    const int bh = blockIdx.y;
    const int b = bh / NH, h = bh % NH;
    const int kvh = h / (NH / NKV);

    __shared__ __align__(16) float Qt[HD][68];   // [d][row]
    __shared__ __align__(16) float Kt[HD][68];   // [d][key]
    __shared__ __align__(16) float Vs[64][68];   // [key][d]
    __shared__ __align__(16) float Ps[64][68];   // [row][key]

    const int tid = threadIdx.x;
    const int rg = tid >> 4;   // 0..15 row group
    const int kg = tid & 15;   // 0..15 key/dim group

    // Load Q tile (transposed)
    for (int f = tid; f < 64 * 16; f += 256) {
        int r = f >> 4, dc = (f & 15) * 4;
        const float* src = g_q + (((size_t)(b * T_) + qb * 64 + r) * NH + h) * HD + dc;
        float4 v = *(const float4*)src;
        Qt[dc + 0][r] = v.x; Qt[dc + 1][r] = v.y;
        Qt[dc + 2][r] = v.z; Qt[dc + 3][r] = v.w;
    }

    float m[4], l[4], o[4][4];
#pragma unroll
    for (int i = 0; i < 4; i++) {
        m[i] = NEG_BIG; l[i] = 0.0f;
#pragma unroll
        for (int j = 0; j < 4; j++) o[i][j] = 0.0f;
    }

    const float scale = 0.125f;  // 1/sqrt(64)

    for (int kb = 0; kb <= qb; kb++) {
        __syncthreads();   // protect Kt/Vs reuse from previous iter
        for (int f = tid; f < 64 * 16; f += 256) {
            int i = f >> 4, dc = (f & 15) * 4;
            size_t kbase = (((size_t)(b * T_) + kb * 64 + i) * NKV + kvh) * HD + dc;
            float4 kk4 = *(const float4*)(g_k + kbase);
            Kt[dc + 0][i] = kk4.x; Kt[dc + 1][i] = kk4.y;
            Kt[dc + 2][i] = kk4.z; Kt[dc + 3][i] = kk4.w;
            float4 vv4 = *(const float4*)(g_v + kbase);
            *(float4*)&Vs[i][dc] = vv4;
        }
        __syncthreads();

        // Scores: s[i][j] = sum_d Q[row][d]*K[key][d]
        float s[4][4];
#pragma unroll
        for (int i = 0; i < 4; i++)
#pragma unroll
            for (int j = 0; j < 4; j++) s[i][j] = 0.0f;

#pragma unroll 8
        for (int d = 0; d < HD; d++) {
            float4 q4 = *(const float4*)(&Qt[d][rg * 4]);
            float4 k4 = *(const float4*)(&Kt[d][kg * 4]);
            float qa[4] = {q4.x, q4.y, q4.z, q4.w};
            float ka[4] = {k4.x, k4.y, k4.z, k4.w};
#pragma unroll
            for (int i = 0; i < 4; i++)
#pragma unroll
                for (int j = 0; j < 4; j++)
                    s[i][j] = fmaf(qa[i], ka[j], s[i][j]);
        }

        // scale + causal mask (only diagonal block)
#pragma unroll
        for (int i = 0; i < 4; i++)
#pragma unroll
            for (int j = 0; j < 4; j++) {
                s[i][j] *= scale;
                if (kb == qb && (kg * 4 + j) > (rg * 4 + i)) s[i][j] = NEG_BIG;
            }

        // Online softmax per row (reduce across 16 kg lanes = contiguous half-warp)
#pragma unroll
        for (int i = 0; i < 4; i++) {
            float rm = fmaxf(fmaxf(s[i][0], s[i][1]), fmaxf(s[i][2], s[i][3]));
#pragma unroll
            for (int off = 8; off >= 1; off >>= 1)
                rm = fmaxf(rm, __shfl_xor_sync(0xffffffffu, rm, off));
            float mnew = fmaxf(m[i], rm);
            float corr = __expf(m[i] - mnew);
            float p0 = __expf(s[i][0] - mnew);
            float p1 = __expf(s[i][1] - mnew);
            float p2 = __expf(s[i][2] - mnew);
            float p3 = __expf(s[i][3] - mnew);
            float psum = (p0 + p1) + (p2 + p3);
#pragma unroll
            for (int off = 8; off >= 1; off >>= 1)
                psum += __shfl_xor_sync(0xffffffffu, psum, off);
            l[i] = l[i] * corr + psum;
#pragma unroll
            for (int j = 0; j < 4; j++) o[i][j] *= corr;
            m[i] = mnew;
            *(float4*)&Ps[rg * 4 + i][kg * 4] = make_float4(p0, p1, p2, p3);
        }
        __syncwarp();   // P rows produced/consumed within the same half-warp

        // O += P * V : thread owns rows rg*4..+4, dims kg*4..+4
#pragma unroll 8
        for (int k = 0; k < 64; k++) {
            float4 v4 = *(const float4*)(&Vs[k][kg * 4]);
#pragma unroll
            for (int i = 0; i < 4; i++) {
                float p = Ps[rg * 4 + i][k];
                o[i][0] = fmaf(p, v4.x, o[i][0]);
                o[i][1] = fmaf(p, v4.y, o[i][1]);
                o[i][2] = fmaf(p, v4.z, o[i][2]);
                o[i][3] = fmaf(p, v4.w, o[i][3]);
            }
        }
    }

    // Normalize + write to g_o laid out [B*T, NH*HD]
#pragma unroll
    for (int i = 0; i < 4; i++) {
        float inv = 1.0f / l[i];
        float* dst = g_o + (((size_t)(b * T_) + qb * 64 + rg * 4 + i) * NH + h) * HD + kg * 4;
        *(float4*)dst = make_float4(o[i][0] * inv, o[i][1] * inv,
                                    o[i][2] * inv, o[i][3] * inv);
    }
}

// ---------------------------------------------------------------------------
// Launch
// ---------------------------------------------------------------------------
extern "C" void kernel_launch(void* const* d_in, const int* in_sizes, int n_in,
                              void* d_out, int out_size)
{
    const float* x   = (const float*)d_in[0];
    const float* cosb= (const float*)d_in[1];
    const float* sinb= (const float*)d_in[2];
    const float* Wq  = (const float*)d_in[3];
    const float* Wk  = (const float*)d_in[4];
    const float* Wv  = (const float*)d_in[5];
    const float* Wo  = (const float*)d_in[6];
    float* out = (float*)d_out;

    float* q; cudaGetSymbolAddress((void**)&q, g_q);
    float* k; cudaGetSymbolAddress((void**)&k, g_k);
    float* v; cudaGetSymbolAddress((void**)&v, g_v);
    float* o; cudaGetSymbolAddress((void**)&o, g_o);

    const int M = B_ * T_;  // 4096

    // QKV projections
    sgemm_nt<<<dim3((NH * HD) / BN, M / BM), 256>>>(x, Wq, q, M, NH * HD, DIM_);
    sgemm_nt<<<dim3((NKV * HD) / BN, M / BM), 256>>>(x, Wk, k, M, NKV * HD, DIM_);
    sgemm_nt<<<dim3((NKV * HD) / BN, M / BM), 256>>>(x, Wv, v, M, NKV * HD, DIM_);

    // RoPE
    {
        int tq = B_ * T_ * NH * (HD / 2);
        rope_kernel<<<(tq + 255) / 256, 256>>>(q, cosb, sinb, NH);
        int tk = B_ * T_ * NKV * (HD / 2);
        rope_kernel<<<(tk + 255) / 256, 256>>>(k, cosb, sinb, NKV);
    }

    // Attention
    attn_kernel<<<dim3(T_ / 64, B_ * NH), 256>>>();

    // Output projection -> d_out
    sgemm_nt<<<dim3(DIM_ / BN, M / BM), 256>>>(o, Wo, out, M, DIM_, DIM_);
}

// round 3
// speedup vs baseline: 1.7710x; 1.7710x over previous
#include <cuda_runtime.h>
#include <cuda_bf16.h>
#include <math.h>
#include <stdint.h>

#define B_   4
#define T_   1024
#define DIM_ 2048
#define NH   32
#define NKV  8
#define HD   64

typedef __nv_bfloat16 bf16;

// ---------------------------------------------------------------------------
// Scratch (__device__ globals; allocation-free rule)
// ---------------------------------------------------------------------------
__device__ float g_q[(size_t)B_ * T_ * NH * HD];
__device__ float g_k[(size_t)B_ * T_ * NKV * HD];
__device__ float g_v[(size_t)B_ * T_ * NKV * HD];
__device__ float g_o[(size_t)B_ * T_ * NH * HD];

__device__ bf16 g_xh[(size_t)B_ * T_ * DIM_];
__device__ bf16 g_xl[(size_t)B_ * T_ * DIM_];
__device__ bf16 g_wqh[(size_t)NH * HD * DIM_];
__device__ bf16 g_wql[(size_t)NH * HD * DIM_];
__device__ bf16 g_wkh[(size_t)NKV * HD * DIM_];
__device__ bf16 g_wkl[(size_t)NKV * HD * DIM_];
__device__ bf16 g_wvh[(size_t)NKV * HD * DIM_];
__device__ bf16 g_wvl[(size_t)NKV * HD * DIM_];
__device__ bf16 g_woh[(size_t)DIM_ * NH * HD];
__device__ bf16 g_wol[(size_t)DIM_ * NH * HD];
__device__ bf16 g_oh[(size_t)B_ * T_ * NH * HD];
__device__ bf16 g_ol[(size_t)B_ * T_ * NH * HD];

// ---------------------------------------------------------------------------
// PTX helpers (portable ISA only: ldmatrix + mma.sync)
// ---------------------------------------------------------------------------
__device__ __forceinline__ uint32_t smem_u32(const void* p) {
    uint32_t a;
    asm("{ .reg .u64 t; cvta.to.shared.u64 t, %1; cvt.u32.u64 %0, t; }"
        : "=r"(a) : "l"(p));
    return a;
}

__device__ __forceinline__ void ldmx4(uint32_t* r, uint32_t addr) {
    asm volatile("ldmatrix.sync.aligned.m8n8.x4.shared.b16 {%0,%1,%2,%3}, [%4];"
                 : "=r"(r[0]), "=r"(r[1]), "=r"(r[2]), "=r"(r[3]) : "r"(addr));
}

__device__ __forceinline__ void mma16816(float* d, const uint32_t* a, const uint32_t* b) {
    asm volatile(
        "mma.sync.aligned.m16n8k16.row.col.f32.bf16.bf16.f32 "
        "{%0,%1,%2,%3}, {%4,%5,%6,%7}, {%8,%9}, {%0,%1,%2,%3};"
        : "+f"(d[0]), "+f"(d[1]), "+f"(d[2]), "+f"(d[3])
        : "r"(a[0]), "r"(a[1]), "r"(a[2]), "r"(a[3]), "r"(b[0]), "r"(b[1]));
}

// ---------------------------------------------------------------------------
// Split fp32 -> (bf16 hi, bf16 lo)
// ---------------------------------------------------------------------------
__global__ void split_kernel(const float4* __restrict__ src,
                             uint2* __restrict__ hi, uint2* __restrict__ lo, int n4)
{
    int i = blockIdx.x * blockDim.x + threadIdx.x;
    if (i >= n4) return;
    float4 a = src[i];
    bf16 hx = __float2bfloat16(a.x);
    bf16 hy = __float2bfloat16(a.y);
    bf16 hz = __float2bfloat16(a.z);
    bf16 hw = __float2bfloat16(a.w);
    bf16 lx = __float2bfloat16(a.x - __bfloat162float(hx));
    bf16 ly = __float2bfloat16(a.y - __bfloat162float(hy));
    bf16 lz = __float2bfloat16(a.z - __bfloat162float(hz));
    bf16 lw = __float2bfloat16(a.w - __bfloat162float(hw));
    __nv_bfloat162 h0 = __halves2bfloat162(hx, hy);
    __nv_bfloat162 h1 = __halves2bfloat162(hz, hw);
    __nv_bfloat162 l0 = __halves2bfloat162(lx, ly);
    __nv_bfloat162 l1 = __halves2bfloat162(lz, lw);
    uint2 hv, lv;
    hv.x = *(uint32_t*)&h0; hv.y = *(uint32_t*)&h1;
    lv.x = *(uint32_t*)&l0; lv.y = *(uint32_t*)&l1;
    hi[i] = hv; lo[i] = lv;
}

// ---------------------------------------------------------------------------
// HMMA GEMM: C[M,N] = Ah*Bh^T + Ah*Bl^T + Al*Bh^T  (fp32 accum)
// A [M,K], B [N,K] bf16 row-major. CTA tile 128x128, BK=32, 256 threads.
// Warps: 2(M) x 4(N), each warp 64x32 = 4 m16-tiles x 4 n8-tiles.
// Smem rows padded to 40 bf16 (80B) -> conflict-free ldmatrix.
// ---------------------------------------------------------------------------
#define GBK 32
#define GST 40   // smem row stride in bf16 elements

__global__ __launch_bounds__(256) void gemm_hmma3(
    const bf16* __restrict__ Ah, const bf16* __restrict__ Al,
    const bf16* __restrict__ Bh, const bf16* __restrict__ Bl,
    float* __restrict__ C, int M, int N, int K)
{
    __shared__ __align__(16) bf16 sAh[128 * GST];
    __shared__ __align__(16) bf16 sAl[128 * GST];
    __shared__ __align__(16) bf16 sBh[128 * GST];
    __shared__ __align__(16) bf16 sBl[128 * GST];

    const int tid  = threadIdx.x;
    const int wid  = tid >> 5;
    const int lane = tid & 31;
    const int m0 = blockIdx.y * 128;
    const int n0 = blockIdx.x * 128;

    const int wm = (wid & 1) * 64;   // warp M offset in tile
    const int wn = (wid >> 1) * 32;  // warp N offset in tile

    float acc[4][4][4];
#pragma unroll
    for (int i = 0; i < 4; i++)
#pragma unroll
        for (int j = 0; j < 4; j++)
#pragma unroll
            for (int c = 0; c < 4; c++) acc[i][j][c] = 0.0f;

    const uint32_t uAh = smem_u32(sAh);
    const uint32_t uAl = smem_u32(sAl);
    const uint32_t uBh = smem_u32(sBh);
    const uint32_t uBl = smem_u32(sBl);

    // ldmatrix address offsets (bytes), depend only on lane
    // A: row = wm + mi*16 + (lane%8) + ((lane>>3)&1)*8 ; col = kk + (lane>>4)*8
    const int aRow = (lane & 7) + ((lane >> 3) & 1) * 8;
    const int aCol = (lane >> 4) * 8;
    // B: row = wn + j*16 + ((lane>>4)*8) + (lane%8) ; col = kk + ((lane>>3)&1)*8
    const int bRow = (lane & 7) + (lane >> 4) * 8;
    const int bCol = ((lane >> 3) & 1) * 8;

    // gmem load mapping: per tile 512 uint4 (128 rows x 4 cols of 8 bf16)
    const int lr = tid >> 1;            // 0..127 row
    const int lc = (tid & 1) * 2;       // uint4 col pair base: 0 or 2

    for (int k0 = 0; k0 < K; k0 += GBK) {
        __syncthreads();
#define LOAD_TILE(dst, src, row0)                                             \
        {                                                                     \
            const bf16* s = (src) + (size_t)((row0) + lr) * K + k0 + lc * 8;  \
            uint4 v0 = *(const uint4*)s;                                      \
            uint4 v1 = *(const uint4*)(s + 8);                                \
            *(uint4*)((dst) + lr * GST + lc * 8)       = v0;                  \
            *(uint4*)((dst) + lr * GST + (lc + 1) * 8) = v1;                  \
        }
        LOAD_TILE(sAh, Ah, m0)
        LOAD_TILE(sAl, Al, m0)
        LOAD_TILE(sBh, Bh, n0)
        LOAD_TILE(sBl, Bl, n0)
#undef LOAD_TILE
        __syncthreads();

#pragma unroll
        for (int kk = 0; kk < GBK; kk += 16) {
            uint32_t ah[4][4], al[4][4], bh[4][2], bl[4][2];
#pragma unroll
            for (int mi = 0; mi < 4; mi++) {
                uint32_t off = (uint32_t)(((wm + mi * 16 + aRow) * GST + kk + aCol) * 2);
                ldmx4(ah[mi], uAh + off);
                ldmx4(al[mi], uAl + off);
            }
#pragma unroll
            for (int j = 0; j < 2; j++) {
                uint32_t off = (uint32_t)(((wn + j * 16 + bRow) * GST + kk + bCol) * 2);
                uint32_t rh[4], rl[4];
                ldmx4(rh, uBh + off);
                ldmx4(rl, uBl + off);
                bh[j * 2][0] = rh[0]; bh[j * 2][1] = rh[1];
                bh[j * 2 + 1][0] = rh[2]; bh[j * 2 + 1][1] = rh[3];
                bl[j * 2][0] = rl[0]; bl[j * 2][1] = rl[1];
                bl[j * 2 + 1][0] = rl[2]; bl[j * 2 + 1][1] = rl[3];
            }
#pragma unroll
            for (int mi = 0; mi < 4; mi++)
#pragma unroll
                for (int nj = 0; nj < 4; nj++) {
                    mma16816(acc[mi][nj], ah[mi], bh[nj]);
                    mma16816(acc[mi][nj], ah[mi], bl[nj]);
                    mma16816(acc[mi][nj], al[mi], bh[nj]);
                }
        }
    }

    // Epilogue: thread t holds c0,c1 at (row=t/4, col=2*(t%4)), c2,c3 at row+8
    const int er = lane >> 2;
    const int ec = (lane & 3) * 2;
#pragma unroll
    for (int mi = 0; mi < 4; mi++)
#pragma unroll
        for (int nj = 0; nj < 4; nj++) {
            float* p0 = C + (size_t)(m0 + wm + mi * 16 + er) * N + n0 + wn + nj * 8 + ec;
            float* p1 = p0 + 8 * N;
            *(float2*)p0 = make_float2(acc[mi][nj][0], acc[mi][nj][1]);
            *(float2*)p1 = make_float2(acc[mi][nj][2], acc[mi][nj][3]);
        }
}

// ---------------------------------------------------------------------------
// RoPE (interleaved pairs), in place. buf layout [B*T, nheads, 64].
// ---------------------------------------------------------------------------
__global__ void rope_kernel(float* __restrict__ buf,
                            const float* __restrict__ cosb,
                            const float* __restrict__ sinb,
                            int nheads)
{
    int idx = blockIdx.x * blockDim.x + threadIdx.x;
    int total = B_ * T_ * nheads * (HD / 2);
    if (idx >= total) return;
    int p  = idx & 31;
    int h  = (idx >> 5) % nheads;
    int bt = idx / (32 * nheads);
    int t  = bt % T_;
    size_t base = ((size_t)bt * nheads + h) * HD + 2 * p;
    float e = buf[base], o = buf[base + 1];
    float c = cosb[t * 32 + p], s = sinb[t * 32 + p];
    buf[base]     = e * c - o * s;
    buf[base + 1] = e * s + o * c;
}

// ---------------------------------------------------------------------------
// Causal GQA flash attention, fp32 SIMT
// ---------------------------------------------------------------------------
#define NEG_BIG (-1e30f)

__global__ __launch_bounds__(256) void attn_kernel()
{
    const int qb = blockIdx.x;
    const int bh = blockIdx.y;
    const int b = bh / NH, h = bh % NH;
    const int kvh = h / (NH / NKV);

    __shared__ __align__(16) float Qt[HD][68];
    __shared__ __align__(16) float Kt[HD][68];
    __shared__ __align__(16) float Vs[64][68];
    __shared__ __align__(16) float Ps[64][68];

    const int tid = threadIdx.x;
    const int rg = tid >> 4;
    const int kg = tid & 15;

    for (int f = tid; f < 64 * 16; f += 256) {
        int r = f >> 4, dc = (f & 15) * 4;
        const float* src = g_q + (((size_t)(b * T_) + qb * 64 + r) * NH + h) * HD + dc;
        float4 v = *(const float4*)src;
        Qt[dc + 0][r] = v.x; Qt[dc + 1][r] = v.y;
        Qt[dc + 2][r] = v.z; Qt[dc + 3][r] = v.w;
    }

    float m[4], l[4], o[4][4];
#pragma unroll
    for (int i = 0; i < 4; i++) {
        m[i] = NEG_BIG; l[i] = 0.0f;
#pragma unroll
        for (int j = 0; j < 4; j++) o[i][j] = 0.0f;
    }

    const float scale = 0.125f;

    for (int kb = 0; kb <= qb; kb++) {
        __syncthreads();
        for (int f = tid; f < 64 * 16; f += 256) {
            int i = f >> 4, dc = (f & 15) * 4;
            size_t kbase = (((size_t)(b * T_) + kb * 64 + i) * NKV + kvh) * HD + dc;
            float4 kk4 = *(const float4*)(g_k + kbase);
            Kt[dc + 0][i] = kk4.x; Kt[dc + 1][i] = kk4.y;
            Kt[dc + 2][i] = kk4.z; Kt[dc + 3][i] = kk4.w;
            float4 vv4 = *(const float4*)(g_v + kbase);
            *(float4*)&Vs[i][dc] = vv4;
        }
        __syncthreads();

        float s[4][4];
#pragma unroll
        for (int i = 0; i < 4; i++)
#pragma unroll
            for (int j = 0; j < 4; j++) s[i][j] = 0.0f;

#pragma unroll 8
        for (int d = 0; d < HD; d++) {
            float4 q4 = *(const float4*)(&Qt[d][rg * 4]);
            float4 k4 = *(const float4*)(&Kt[d][kg * 4]);
            float qa[4] = {q4.x, q4.y, q4.z, q4.w};
            float ka[4] = {k4.x, k4.y, k4.z, k4.w};
#pragma unroll
            for (int i = 0; i < 4; i++)
#pragma unroll
                for (int j = 0; j < 4; j++)
                    s[i][j] = fmaf(qa[i], ka[j], s[i][j]);
        }

#pragma unroll
        for (int i = 0; i < 4; i++)
#pragma unroll
            for (int j = 0; j < 4; j++) {
                s[i][j] *= scale;
                if (kb == qb && (kg * 4 + j) > (rg * 4 + i)) s[i][j] = NEG_BIG;
            }

#pragma unroll
        for (int i = 0; i < 4; i++) {
            float rm = fmaxf(fmaxf(s[i][0], s[i][1]), fmaxf(s[i][2], s[i][3]));
#pragma unroll
            for (int off = 8; off >= 1; off >>= 1)
                rm = fmaxf(rm, __shfl_xor_sync(0xffffffffu, rm, off));
            float mnew = fmaxf(m[i], rm);
            float corr = __expf(m[i] - mnew);
            float p0 = __expf(s[i][0] - mnew);
            float p1 = __expf(s[i][1] - mnew);
            float p2 = __expf(s[i][2] - mnew);
            float p3 = __expf(s[i][3] - mnew);
            float psum = (p0 + p1) + (p2 + p3);
#pragma unroll
            for (int off = 8; off >= 1; off >>= 1)
                psum += __shfl_xor_sync(0xffffffffu, psum, off);
            l[i] = l[i] * corr + psum;
#pragma unroll
            for (int j = 0; j < 4; j++) o[i][j] *= corr;
            m[i] = mnew;
            *(float4*)&Ps[rg * 4 + i][kg * 4] = make_float4(p0, p1, p2, p3);
        }
        __syncwarp();

#pragma unroll 8
        for (int k = 0; k < 64; k++) {
            float4 v4 = *(const float4*)(&Vs[k][kg * 4]);
#pragma unroll
            for (int i = 0; i < 4; i++) {
                float p = Ps[rg * 4 + i][k];
                o[i][0] = fmaf(p, v4.x, o[i][0]);
                o[i][1] = fmaf(p, v4.y, o[i][1]);
                o[i][2] = fmaf(p, v4.z, o[i][2]);
                o[i][3] = fmaf(p, v4.w, o[i][3]);
            }
        }
    }

#pragma unroll
    for (int i = 0; i < 4; i++) {
        float inv = 1.0f / l[i];
        float* dst = g_o + (((size_t)(b * T_) + qb * 64 + rg * 4 + i) * NH + h) * HD + kg * 4;
        *(float4*)dst = make_float4(o[i][0] * inv, o[i][1] * inv,
                                    o[i][2] * inv, o[i][3] * inv);
    }
}

// ---------------------------------------------------------------------------
// Launch
// ---------------------------------------------------------------------------
extern "C" void kernel_launch(void* const* d_in, const int* in_sizes, int n_in,
                              void* d_out, int out_size)
{
    const float* x    = (const float*)d_in[0];
    const float* cosb = (const float*)d_in[1];
    const float* sinb = (const float*)d_in[2];
    const float* Wq   = (const float*)d_in[3];
    const float* Wk   = (const float*)d_in[4];
    const float* Wv   = (const float*)d_in[5];
    const float* Wo   = (const float*)d_in[6];
    float* out = (float*)d_out;

    float* q; cudaGetSymbolAddress((void**)&q, g_q);
    float* k; cudaGetSymbolAddress((void**)&k, g_k);
    float* v; cudaGetSymbolAddress((void**)&v, g_v);
    float* o; cudaGetSymbolAddress((void**)&o, g_o);
    bf16 *xh, *xl, *wqh, *wql, *wkh, *wkl, *wvh, *wvl, *woh, *wol, *oh, *ol;
    cudaGetSymbolAddress((void**)&xh, g_xh);   cudaGetSymbolAddress((void**)&xl, g_xl);
    cudaGetSymbolAddress((void**)&wqh, g_wqh); cudaGetSymbolAddress((void**)&wql, g_wql);
    cudaGetSymbolAddress((void**)&wkh, g_wkh); cudaGetSymbolAddress((void**)&wkl, g_wkl);
    cudaGetSymbolAddress((void**)&wvh, g_wvh); cudaGetSymbolAddress((void**)&wvl, g_wvl);
    cudaGetSymbolAddress((void**)&woh, g_woh); cudaGetSymbolAddress((void**)&wol, g_wol);
    cudaGetSymbolAddress((void**)&oh, g_oh);   cudaGetSymbolAddress((void**)&ol, g_ol);

    const int M = B_ * T_;  // 4096

    // Splits
    {
        int n4;
        n4 = M * DIM_ / 4;
        split_kernel<<<(n4 + 255) / 256, 256>>>((const float4*)x, (uint2*)xh, (uint2*)xl, n4);
        n4 = NH * HD * DIM_ / 4;
        split_kernel<<<(n4 + 255) / 256, 256>>>((const float4*)Wq, (uint2*)wqh, (uint2*)wql, n4);
        n4 = NKV * HD * DIM_ / 4;
        split_kernel<<<(n4 + 255) / 256, 256>>>((const float4*)Wk, (uint2*)wkh, (uint2*)wkl, n4);
        split_kernel<<<(n4 + 255) / 256, 256>>>((const float4*)Wv, (uint2*)wvh, (uint2*)wvl, n4);
        n4 = DIM_ * NH * HD / 4;
        split_kernel<<<(n4 + 255) / 256, 256>>>((const float4*)Wo, (uint2*)woh, (uint2*)wol, n4);
    }

    // QKV projections (tensor cores via mma.sync)
    gemm_hmma3<<<dim3((NH * HD) / 128, M / 128), 256>>>(xh, xl, wqh, wql, q, M, NH * HD, DIM_);
    gemm_hmma3<<<dim3((NKV * HD) / 128, M / 128), 256>>>(xh, xl, wkh, wkl, k, M, NKV * HD, DIM_);
    gemm_hmma3<<<dim3((NKV * HD) / 128, M / 128), 256>>>(xh, xl, wvh, wvl, v, M, NKV * HD, DIM_);

    // RoPE
    {
        int tq = B_ * T_ * NH * (HD / 2);
        rope_kernel<<<(tq + 255) / 256, 256>>>(q, cosb, sinb, NH);
        int tk = B_ * T_ * NKV * (HD / 2);
        rope_kernel<<<(tk + 255) / 256, 256>>>(k, cosb, sinb, NKV);
    }

    // Attention (fp32 SIMT)
    attn_kernel<<<dim3(T_ / 64, B_ * NH), 256>>>();

    // Split attention output, then output projection
    {
        int n4 = M * DIM_ / 4;
        split_kernel<<<(n4 + 255) / 256, 256>>>((const float4*)o, (uint2*)oh, (uint2*)ol, n4);
    }
    gemm_hmma3<<<dim3(DIM_ / 128, M / 128), 256>>>(oh, ol, woh, wol, out, M, DIM_, DIM_);
}

// round 4
// speedup vs baseline: 1.8302x; 1.0334x over previous
#include <cuda_runtime.h>
#include <cuda_bf16.h>
#include <math.h>
#include <stdint.h>

#define B_   4
#define T_   1024
#define DIM_ 2048
#define NH   32
#define NKV  8
#define HD   64

typedef __nv_bfloat16 bf16;

// ---------------------------------------------------------------------------
// Scratch (__device__ globals; allocation-free rule)
// ---------------------------------------------------------------------------
__device__ float g_q[(size_t)B_ * T_ * NH * HD];
__device__ float g_k[(size_t)B_ * T_ * NKV * HD];
__device__ float g_v[(size_t)B_ * T_ * NKV * HD];

__device__ bf16 g_xh[(size_t)B_ * T_ * DIM_];
__device__ bf16 g_xl[(size_t)B_ * T_ * DIM_];
__device__ bf16 g_wqh[(size_t)NH * HD * DIM_];
__device__ bf16 g_wql[(size_t)NH * HD * DIM_];
__device__ bf16 g_wkh[(size_t)NKV * HD * DIM_];
__device__ bf16 g_wkl[(size_t)NKV * HD * DIM_];
__device__ bf16 g_wvh[(size_t)NKV * HD * DIM_];
__device__ bf16 g_wvl[(size_t)NKV * HD * DIM_];
__device__ bf16 g_woh[(size_t)DIM_ * NH * HD];
__device__ bf16 g_wol[(size_t)DIM_ * NH * HD];
__device__ bf16 g_oh[(size_t)B_ * T_ * NH * HD];
__device__ bf16 g_ol[(size_t)B_ * T_ * NH * HD];

// ---------------------------------------------------------------------------
// PTX helpers (portable ISA: ldmatrix + mma.sync + cp.async)
// ---------------------------------------------------------------------------
__device__ __forceinline__ uint32_t smem_u32(const void* p) {
    uint32_t a;
    asm("{ .reg .u64 t; cvta.to.shared.u64 t, %1; cvt.u32.u64 %0, t; }"
        : "=r"(a) : "l"(p));
    return a;
}

__device__ __forceinline__ void ldmx4(uint32_t* r, uint32_t addr) {
    asm volatile("ldmatrix.sync.aligned.m8n8.x4.shared.b16 {%0,%1,%2,%3}, [%4];"
                 : "=r"(r[0]), "=r"(r[1]), "=r"(r[2]), "=r"(r[3]) : "r"(addr));
}

__device__ __forceinline__ void mma16816(float* d, const uint32_t* a, const uint32_t* b) {
    asm volatile(
        "mma.sync.aligned.m16n8k16.row.col.f32.bf16.bf16.f32 "
        "{%0,%1,%2,%3}, {%4,%5,%6,%7}, {%8,%9}, {%0,%1,%2,%3};"
        : "+f"(d[0]), "+f"(d[1]), "+f"(d[2]), "+f"(d[3])
        : "r"(a[0]), "r"(a[1]), "r"(a[2]), "r"(a[3]), "r"(b[0]), "r"(b[1]));
}

__device__ __forceinline__ void cp16(uint32_t dst, const void* src) {
    asm volatile("cp.async.cg.shared.global [%0], [%1], 16;"
                 :: "r"(dst), "l"(src) : "memory");
}
#define CP_COMMIT() asm volatile("cp.async.commit_group;" ::: "memory")
#define CP_WAIT(n)  asm volatile("cp.async.wait_group %0;" :: "n"(n) : "memory")

// ---------------------------------------------------------------------------
// Split fp32 -> (bf16 hi, bf16 lo)
// ---------------------------------------------------------------------------
__global__ void split_kernel(const float4* __restrict__ src,
                             uint2* __restrict__ hi, uint2* __restrict__ lo, int n4)
{
    int i = blockIdx.x * blockDim.x + threadIdx.x;
    if (i >= n4) return;
    float4 a = src[i];
    bf16 hx = __float2bfloat16(a.x);
    bf16 hy = __float2bfloat16(a.y);
    bf16 hz = __float2bfloat16(a.z);
    bf16 hw = __float2bfloat16(a.w);
    bf16 lx = __float2bfloat16(a.x - __bfloat162float(hx));
    bf16 ly = __float2bfloat16(a.y - __bfloat162float(hy));
    bf16 lz = __float2bfloat16(a.z - __bfloat162float(hz));
    bf16 lw = __float2bfloat16(a.w - __bfloat162float(hw));
    __nv_bfloat162 h0 = __halves2bfloat162(hx, hy);
    __nv_bfloat162 h1 = __halves2bfloat162(hz, hw);
    __nv_bfloat162 l0 = __halves2bfloat162(lx, ly);
    __nv_bfloat162 l1 = __halves2bfloat162(lz, lw);
    uint2 hv, lv;
    hv.x = *(uint32_t*)&h0; hv.y = *(uint32_t*)&h1;
    lv.x = *(uint32_t*)&l0; lv.y = *(uint32_t*)&l1;
    hi[i] = hv; lo[i] = lv;
}

// ---------------------------------------------------------------------------
// HMMA GEMM, cp.async double-buffered:
//   C[M,N] = Ah*Bh^T + Ah*Bl^T + Al*Bh^T   (fp32 accum)
// A [M,K], B [N,K] bf16 row-major. CTA tile 128x128, BK=32, 256 threads.
// Warps 2(M) x 4(N); smem rows padded to 40 bf16 (80B) -> conflict-free ldmatrix.
// Optional fused RoPE epilogue (rope!=0): head period 64, interleaved pairs.
// ---------------------------------------------------------------------------
#define GBK 32
#define GST 40
#define TILE_B  (128 * GST * 2)          // 10240 bytes per tile
#define STAGE_B (4 * TILE_B)             // 40960 bytes per stage
#define GEMM_SMEM (2 * STAGE_B)          // 81920 bytes

__global__ __launch_bounds__(256) void gemm_hmma3(
    const bf16* __restrict__ Ah, const bf16* __restrict__ Al,
    const bf16* __restrict__ Bh, const bf16* __restrict__ Bl,
    float* __restrict__ C, int M, int N, int K,
    const float* __restrict__ cosb, const float* __restrict__ sinb, int rope)
{
    extern __shared__ __align__(16) bf16 smem[];
    const uint32_t uS = smem_u32(smem);

    const int tid  = threadIdx.x;
    const int wid  = tid >> 5;
    const int lane = tid & 31;
    const int m0 = blockIdx.y * 128;
    const int n0 = blockIdx.x * 128;

    const int wm = (wid & 1) * 64;
    const int wn = (wid >> 1) * 32;

    float acc[4][4][4];
#pragma unroll
    for (int i = 0; i < 4; i++)
#pragma unroll
        for (int j = 0; j < 4; j++)
#pragma unroll
            for (int c = 0; c < 4; c++) acc[i][j][c] = 0.0f;

    // ldmatrix lane addressing
    const int aRow = (lane & 7) + ((lane >> 3) & 1) * 8;
    const int aCol = (lane >> 4) * 8;
    const int bRow = (lane & 7) + (lane >> 4) * 8;
    const int bCol = ((lane >> 3) & 1) * 8;

    // gmem->smem mapping: lr row 0..127, lc in {0,2} (16-bf16 chunks)
    const int lr = tid >> 1;
    const int lc = (tid & 1) * 2;

    const bf16* gA_h = Ah + (size_t)(m0 + lr) * K + lc * 8;
    const bf16* gA_l = Al + (size_t)(m0 + lr) * K + lc * 8;
    const bf16* gB_h = Bh + (size_t)(n0 + lr) * K + lc * 8;
    const bf16* gB_l = Bl + (size_t)(n0 + lr) * K + lc * 8;
    const uint32_t dRow = uS + lr * (GST * 2) + lc * 16;

#define ISSUE_STAGE(buf, k0)                                              \
    {                                                                     \
        uint32_t d = dRow + (buf) * STAGE_B;                              \
        cp16(d,              gA_h + (k0));                                \
        cp16(d + 16,         gA_h + (k0) + 8);                            \
        cp16(d + TILE_B,     gA_l + (k0));                                \
        cp16(d + TILE_B + 16,gA_l + (k0) + 8);                            \
        cp16(d + 2*TILE_B,      gB_h + (k0));                             \
        cp16(d + 2*TILE_B + 16, gB_h + (k0) + 8);                         \
        cp16(d + 3*TILE_B,      gB_l + (k0));                             \
        cp16(d + 3*TILE_B + 16, gB_l + (k0) + 8);                         \
    }

    const int niter = K / GBK;
    ISSUE_STAGE(0, 0)
    CP_COMMIT();

    for (int it = 0; it < niter; it++) {
        const int buf = it & 1;
        if (it + 1 < niter) {
            ISSUE_STAGE(buf ^ 1, (it + 1) * GBK)
            CP_COMMIT();
            CP_WAIT(1);
        } else {
            CP_WAIT(0);
        }
        __syncthreads();

        const uint32_t uAh = uS + buf * STAGE_B;
        const uint32_t uAl = uAh + TILE_B;
        const uint32_t uBh = uAh + 2 * TILE_B;
        const uint32_t uBl = uAh + 3 * TILE_B;

#pragma unroll
        for (int kk = 0; kk < GBK; kk += 16) {
            uint32_t ah[4][4], al[4][4], bh[4][2], bl[4][2];
#pragma unroll
            for (int mi = 0; mi < 4; mi++) {
                uint32_t off = (uint32_t)(((wm + mi * 16 + aRow) * GST + kk + aCol) * 2);
                ldmx4(ah[mi], uAh + off);
                ldmx4(al[mi], uAl + off);
            }
#pragma unroll
            for (int j = 0; j < 2; j++) {
                uint32_t off = (uint32_t)(((wn + j * 16 + bRow) * GST + kk + bCol) * 2);
                uint32_t rh[4], rl[4];
                ldmx4(rh, uBh + off);
                ldmx4(rl, uBl + off);
                bh[j * 2][0] = rh[0]; bh[j * 2][1] = rh[1];
                bh[j * 2 + 1][0] = rh[2]; bh[j * 2 + 1][1] = rh[3];
                bl[j * 2][0] = rl[0]; bl[j * 2][1] = rl[1];
                bl[j * 2 + 1][0] = rl[2]; bl[j * 2 + 1][1] = rl[3];
            }
#pragma unroll
            for (int mi = 0; mi < 4; mi++)
#pragma unroll
                for (int nj = 0; nj < 4; nj++) {
                    mma16816(acc[mi][nj], ah[mi], bh[nj]);
                    mma16816(acc[mi][nj], ah[mi], bl[nj]);
                    mma16816(acc[mi][nj], al[mi], bh[nj]);
                }
        }
        __syncthreads();
    }
#undef ISSUE_STAGE

    // Epilogue (+ optional fused RoPE; cols (ec, ec+1) are an even/odd pair)
    const int er = lane >> 2;
    const int ec = (lane & 3) * 2;
#pragma unroll
    for (int mi = 0; mi < 4; mi++)
#pragma unroll
        for (int nj = 0; nj < 4; nj++) {
            float v0 = acc[mi][nj][0], v1 = acc[mi][nj][1];
            float v2 = acc[mi][nj][2], v3 = acc[mi][nj][3];
            const int gm = m0 + wm + mi * 16 + er;
            const int n  = n0 + wn + nj * 8 + ec;
            if (rope) {
                const int p = (n & 63) >> 1;
                const int t0 = gm & (T_ - 1);
                const int t1 = (gm + 8) & (T_ - 1);
                float c0 = cosb[t0 * 32 + p], s0 = sinb[t0 * 32 + p];
                float c1 = cosb[t1 * 32 + p], s1 = sinb[t1 * 32 + p];
                float e = v0, o = v1;
                v0 = e * c0 - o * s0; v1 = e * s0 + o * c0;
                e = v2; o = v3;
                v2 = e * c1 - o * s1; v3 = e * s1 + o * c1;
            }
            float* p0 = C + (size_t)gm * N + n;
            *(float2*)p0           = make_float2(v0, v1);
            *(float2*)(p0 + 8 * N) = make_float2(v2, v3);
        }
}

// ---------------------------------------------------------------------------
// Causal GQA flash attention, fp32 SIMT; epilogue writes split bf16 hi/lo.
// ---------------------------------------------------------------------------
#define NEG_BIG (-1e30f)

__global__ __launch_bounds__(256) void attn_kernel()
{
    const int qb = blockIdx.x;
    const int bh = blockIdx.y;
    const int b = bh / NH, h = bh % NH;
    const int kvh = h / (NH / NKV);

    __shared__ __align__(16) float Qt[HD][68];
    __shared__ __align__(16) float Kt[HD][68];
    __shared__ __align__(16) float Vs[64][68];
    __shared__ __align__(16) float Ps[64][68];

    const int tid = threadIdx.x;
    const int rg = tid >> 4;
    const int kg = tid & 15;

    for (int f = tid; f < 64 * 16; f += 256) {
        int r = f >> 4, dc = (f & 15) * 4;
        const float* src = g_q + (((size_t)(b * T_) + qb * 64 + r) * NH + h) * HD + dc;
        float4 v = *(const float4*)src;
        Qt[dc + 0][r] = v.x; Qt[dc + 1][r] = v.y;
        Qt[dc + 2][r] = v.z; Qt[dc + 3][r] = v.w;
    }

    float m[4], l[4], o[4][4];
#pragma unroll
    for (int i = 0; i < 4; i++) {
        m[i] = NEG_BIG; l[i] = 0.0f;
#pragma unroll
        for (int j = 0; j < 4; j++) o[i][j] = 0.0f;
    }

    const float scale = 0.125f;

    for (int kb = 0; kb <= qb; kb++) {
        __syncthreads();
        for (int f = tid; f < 64 * 16; f += 256) {
            int i = f >> 4, dc = (f & 15) * 4;
            size_t kbase = (((size_t)(b * T_) + kb * 64 + i) * NKV + kvh) * HD + dc;
            float4 kk4 = *(const float4*)(g_k + kbase);
            Kt[dc + 0][i] = kk4.x; Kt[dc + 1][i] = kk4.y;
            Kt[dc + 2][i] = kk4.z; Kt[dc + 3][i] = kk4.w;
            float4 vv4 = *(const float4*)(g_v + kbase);
            *(float4*)&Vs[i][dc] = vv4;
        }
        __syncthreads();

        float s[4][4];
#pragma unroll
        for (int i = 0; i < 4; i++)
#pragma unroll
            for (int j = 0; j < 4; j++) s[i][j] = 0.0f;

#pragma unroll 8
        for (int d = 0; d < HD; d++) {
            float4 q4 = *(const float4*)(&Qt[d][rg * 4]);
            float4 k4 = *(const float4*)(&Kt[d][kg * 4]);
            float qa[4] = {q4.x, q4.y, q4.z, q4.w};
            float ka[4] = {k4.x, k4.y, k4.z, k4.w};
#pragma unroll
            for (int i = 0; i < 4; i++)
#pragma unroll
                for (int j = 0; j < 4; j++)
                    s[i][j] = fmaf(qa[i], ka[j], s[i][j]);
        }

#pragma unroll
        for (int i = 0; i < 4; i++)
#pragma unroll
            for (int j = 0; j < 4; j++) {
                s[i][j] *= scale;
                if (kb == qb && (kg * 4 + j) > (rg * 4 + i)) s[i][j] = NEG_BIG;
            }

#pragma unroll
        for (int i = 0; i < 4; i++) {
            float rm = fmaxf(fmaxf(s[i][0], s[i][1]), fmaxf(s[i][2], s[i][3]));
#pragma unroll
            for (int off = 8; off >= 1; off >>= 1)
                rm = fmaxf(rm, __shfl_xor_sync(0xffffffffu, rm, off));
            float mnew = fmaxf(m[i], rm);
            float corr = __expf(m[i] - mnew);
            float p0 = __expf(s[i][0] - mnew);
            float p1 = __expf(s[i][1] - mnew);
            float p2 = __expf(s[i][2] - mnew);
            float p3 = __expf(s[i][3] - mnew);
            float psum = (p0 + p1) + (p2 + p3);
#pragma unroll
            for (int off = 8; off >= 1; off >>= 1)
                psum += __shfl_xor_sync(0xffffffffu, psum, off);
            l[i] = l[i] * corr + psum;
#pragma unroll
            for (int j = 0; j < 4; j++) o[i][j] *= corr;
            m[i] = mnew;
            *(float4*)&Ps[rg * 4 + i][kg * 4] = make_float4(p0, p1, p2, p3);
        }
        __syncwarp();

#pragma unroll 8
        for (int k = 0; k < 64; k++) {
            float4 v4 = *(const float4*)(&Vs[k][kg * 4]);
#pragma unroll
            for (int i = 0; i < 4; i++) {
                float p = Ps[rg * 4 + i][k];
                o[i][0] = fmaf(p, v4.x, o[i][0]);
                o[i][1] = fmaf(p, v4.y, o[i][1]);
                o[i][2] = fmaf(p, v4.z, o[i][2]);
                o[i][3] = fmaf(p, v4.w, o[i][3]);
            }
        }
    }

    // Normalize, split to bf16 hi/lo, write g_oh/g_ol [token, NH*HD]
#pragma unroll
    for (int i = 0; i < 4; i++) {
        float inv = 1.0f / l[i];
        float f[4];
#pragma unroll
        for (int j = 0; j < 4; j++) f[j] = o[i][j] * inv;
        bf16 hh[4], ll[4];
#pragma unroll
        for (int j = 0; j < 4; j++) {
            hh[j] = __float2bfloat16(f[j]);
            ll[j] = __float2bfloat16(f[j] - __bfloat162float(hh[j]));
        }
        size_t eoff = (((size_t)(b * T_) + qb * 64 + rg * 4 + i) * NH + h) * HD + kg * 4;
        __nv_bfloat162 h0 = __halves2bfloat162(hh[0], hh[1]);
        __nv_bfloat162 h1 = __halves2bfloat162(hh[2], hh[3]);
        __nv_bfloat162 l0 = __halves2bfloat162(ll[0], ll[1]);
        __nv_bfloat162 l1 = __halves2bfloat162(ll[2], ll[3]);
        uint2 hv, lv;
        hv.x = *(uint32_t*)&h0; hv.y = *(uint32_t*)&h1;
        lv.x = *(uint32_t*)&l0; lv.y = *(uint32_t*)&l1;
        *(uint2*)(g_oh + eoff) = hv;
        *(uint2*)(g_ol + eoff) = lv;
    }
}

// ---------------------------------------------------------------------------
// Launch
// ---------------------------------------------------------------------------
extern "C" void kernel_launch(void* const* d_in, const int* in_sizes, int n_in,
                              void* d_out, int out_size)
{
    const float* x    = (const float*)d_in[0];
    const float* cosb = (const float*)d_in[1];
    const float* sinb = (const float*)d_in[2];
    const float* Wq   = (const float*)d_in[3];
    const float* Wk   = (const float*)d_in[4];
    const float* Wv   = (const float*)d_in[5];
    const float* Wo   = (const float*)d_in[6];
    float* out = (float*)d_out;

    float* q; cudaGetSymbolAddress((void**)&q, g_q);
    float* k; cudaGetSymbolAddress((void**)&k, g_k);
    float* v; cudaGetSymbolAddress((void**)&v, g_v);
    bf16 *xh, *xl, *wqh, *wql, *wkh, *wkl, *wvh, *wvl, *woh, *wol, *oh, *ol;
    cudaGetSymbolAddress((void**)&xh, g_xh);   cudaGetSymbolAddress((void**)&xl, g_xl);
    cudaGetSymbolAddress((void**)&wqh, g_wqh); cudaGetSymbolAddress((void**)&wql, g_wql);
    cudaGetSymbolAddress((void**)&wkh, g_wkh); cudaGetSymbolAddress((void**)&wkl, g_wkl);
    cudaGetSymbolAddress((void**)&wvh, g_wvh); cudaGetSymbolAddress((void**)&wvl, g_wvl);
    cudaGetSymbolAddress((void**)&woh, g_woh); cudaGetSymbolAddress((void**)&wol, g_wol);
    cudaGetSymbolAddress((void**)&oh, g_oh);   cudaGetSymbolAddress((void**)&ol, g_ol);

    cudaFuncSetAttribute(gemm_hmma3, cudaFuncAttributeMaxDynamicSharedMemorySize,
                         GEMM_SMEM);

    const int M = B_ * T_;  // 4096

    // Splits
    {
        int n4;
        n4 = M * DIM_ / 4;
        split_kernel<<<(n4 + 255) / 256, 256>>>((const float4*)x, (uint2*)xh, (uint2*)xl, n4);
        n4 = NH * HD * DIM_ / 4;
        split_kernel<<<(n4 + 255) / 256, 256>>>((const float4*)Wq, (uint2*)wqh, (uint2*)wql, n4);
        n4 = NKV * HD * DIM_ / 4;
        split_kernel<<<(n4 + 255) / 256, 256>>>((const float4*)Wk, (uint2*)wkh, (uint2*)wkl, n4);
        split_kernel<<<(n4 + 255) / 256, 256>>>((const float4*)Wv, (uint2*)wvh, (uint2*)wvl, n4);
        n4 = DIM_ * NH * HD / 4;
        split_kernel<<<(n4 + 255) / 256, 256>>>((const float4*)Wo, (uint2*)woh, (uint2*)wol, n4);
    }

    // QKV projections (RoPE fused into Q/K epilogues)
    gemm_hmma3<<<dim3((NH * HD) / 128, M / 128), 256, GEMM_SMEM>>>(
        xh, xl, wqh, wql, q, M, NH * HD, DIM_, cosb, sinb, 1);
    gemm_hmma3<<<dim3((NKV * HD) / 128, M / 128), 256, GEMM_SMEM>>>(
        xh, xl, wkh, wkl, k, M, NKV * HD, DIM_, cosb, sinb, 1);
    gemm_hmma3<<<dim3((NKV * HD) / 128, M / 128), 256, GEMM_SMEM>>>(
        xh, xl, wvh, wvl, v, M, NKV * HD, DIM_, cosb, sinb, 0);

    // Attention (fp32 SIMT, writes split bf16 output directly)
    attn_kernel<<<dim3(T_ / 64, B_ * NH), 256>>>();

    // Output projection
    gemm_hmma3<<<dim3(DIM_ / 128, M / 128), 256, GEMM_SMEM>>>(
        oh, ol, woh, wol, out, M, DIM_, DIM_, cosb, sinb, 0);
}

// round 5
// speedup vs baseline: 2.4718x; 1.3506x over previous
#include <cuda_runtime.h>
#include <cuda_bf16.h>
#include <math.h>
#include <stdint.h>

#define B_   4
#define T_   1024
#define DIM_ 2048
#define NH   32
#define NKV  8
#define HD   64

typedef __nv_bfloat16 bf16;

// ---------------------------------------------------------------------------
// Scratch (__device__ globals; allocation-free rule)
// ---------------------------------------------------------------------------
__device__ bf16 g_xh[(size_t)B_ * T_ * DIM_];
__device__ bf16 g_xl[(size_t)B_ * T_ * DIM_];
__device__ bf16 g_wqh[(size_t)NH * HD * DIM_];
__device__ bf16 g_wql[(size_t)NH * HD * DIM_];
__device__ bf16 g_wkh[(size_t)NKV * HD * DIM_];
__device__ bf16 g_wkl[(size_t)NKV * HD * DIM_];
__device__ bf16 g_wvh[(size_t)NKV * HD * DIM_];
__device__ bf16 g_wvl[(size_t)NKV * HD * DIM_];
__device__ bf16 g_woh[(size_t)DIM_ * NH * HD];
__device__ bf16 g_wol[(size_t)DIM_ * NH * HD];

__device__ bf16 g_qh[(size_t)B_ * T_ * NH * HD];
__device__ bf16 g_ql[(size_t)B_ * T_ * NH * HD];
__device__ bf16 g_kh[(size_t)B_ * T_ * NKV * HD];
__device__ bf16 g_kl[(size_t)B_ * T_ * NKV * HD];
__device__ bf16 g_vh[(size_t)B_ * T_ * NKV * HD];
__device__ bf16 g_vl[(size_t)B_ * T_ * NKV * HD];
__device__ bf16 g_oh[(size_t)B_ * T_ * NH * HD];
__device__ bf16 g_ol[(size_t)B_ * T_ * NH * HD];

// ---------------------------------------------------------------------------
// PTX helpers (portable ISA: ldmatrix + mma.sync + cp.async)
// ---------------------------------------------------------------------------
__device__ __forceinline__ uint32_t smem_u32(const void* p) {
    uint32_t a;
    asm("{ .reg .u64 t; cvta.to.shared.u64 t, %1; cvt.u32.u64 %0, t; }"
        : "=r"(a) : "l"(p));
    return a;
}

__device__ __forceinline__ void ldmx4(uint32_t* r, uint32_t addr) {
    asm volatile("ldmatrix.sync.aligned.m8n8.x4.shared.b16 {%0,%1,%2,%3}, [%4];"
                 : "=r"(r[0]), "=r"(r[1]), "=r"(r[2]), "=r"(r[3]) : "r"(addr));
}

__device__ __forceinline__ void ldmx4t(uint32_t* r, uint32_t addr) {
    asm volatile("ldmatrix.sync.aligned.m8n8.x4.trans.shared.b16 {%0,%1,%2,%3}, [%4];"
                 : "=r"(r[0]), "=r"(r[1]), "=r"(r[2]), "=r"(r[3]) : "r"(addr));
}

__device__ __forceinline__ void mma16816(float* d, const uint32_t* a, const uint32_t* b) {
    asm volatile(
        "mma.sync.aligned.m16n8k16.row.col.f32.bf16.bf16.f32 "
        "{%0,%1,%2,%3}, {%4,%5,%6,%7}, {%8,%9}, {%0,%1,%2,%3};"
        : "+f"(d[0]), "+f"(d[1]), "+f"(d[2]), "+f"(d[3])
        : "r"(a[0]), "r"(a[1]), "r"(a[2]), "r"(a[3]), "r"(b[0]), "r"(b[1]));
}

__device__ __forceinline__ void cp16(uint32_t dst, const void* src) {
    asm volatile("cp.async.cg.shared.global [%0], [%1], 16;"
                 :: "r"(dst), "l"(src) : "memory");
}
#define CP_COMMIT() asm volatile("cp.async.commit_group;" ::: "memory")
#define CP_WAIT(n)  asm volatile("cp.async.wait_group %0;" :: "n"(n) : "memory")

// ---------------------------------------------------------------------------
// Split fp32 -> (bf16 hi, bf16 lo)
// ---------------------------------------------------------------------------
__global__ void split_kernel(const float4* __restrict__ src,
                             uint2* __restrict__ hi, uint2* __restrict__ lo, int n4)
{
    int i = blockIdx.x * blockDim.x + threadIdx.x;
    if (i >= n4) return;
    float4 a = src[i];
    bf16 hx = __float2bfloat16(a.x);
    bf16 hy = __float2bfloat16(a.y);
    bf16 hz = __float2bfloat16(a.z);
    bf16 hw = __float2bfloat16(a.w);
    bf16 lx = __float2bfloat16(a.x - __bfloat162float(hx));
    bf16 ly = __float2bfloat16(a.y - __bfloat162float(hy));
    bf16 lz = __float2bfloat16(a.z - __bfloat162float(hz));
    bf16 lw = __float2bfloat16(a.w - __bfloat162float(hw));
    __nv_bfloat162 h0 = __halves2bfloat162(hx, hy);
    __nv_bfloat162 h1 = __halves2bfloat162(hz, hw);
    __nv_bfloat162 l0 = __halves2bfloat162(lx, ly);
    __nv_bfloat162 l1 = __halves2bfloat162(lz, lw);
    uint2 hv, lv;
    hv.x = *(uint32_t*)&h0; hv.y = *(uint32_t*)&h1;
    lv.x = *(uint32_t*)&l0; lv.y = *(uint32_t*)&l1;
    hi[i] = hv; lo[i] = lv;
}

// ---------------------------------------------------------------------------
// HMMA GEMM, cp.async double-buffered:
//   C = Ah*Bh^T + Ah*Bl^T + Al*Bh^T   (fp32 accum)
// mode 0: write fp32 C. mode 1: RoPE + scale + split -> Ch/Cl. mode 2: scale+split.
// ---------------------------------------------------------------------------
#define GBK 32
#define GST 40
#define TILE_B  (128 * GST * 2)
#define STAGE_B (4 * TILE_B)
#define GEMM_SMEM (2 * STAGE_B)

__global__ __launch_bounds__(256) void gemm_hmma3(
    const bf16* __restrict__ Ah, const bf16* __restrict__ Al,
    const bf16* __restrict__ Bh, const bf16* __restrict__ Bl,
    float* __restrict__ C, bf16* __restrict__ Ch, bf16* __restrict__ Cl,
    int M, int N, int K,
    const float* __restrict__ cosb, const float* __restrict__ sinb,
    int mode, float outscale)
{
    extern __shared__ __align__(16) bf16 smem[];
    const uint32_t uS = smem_u32(smem);

    const int tid  = threadIdx.x;
    const int wid  = tid >> 5;
    const int lane = tid & 31;
    const int m0 = blockIdx.y * 128;
    const int n0 = blockIdx.x * 128;

    const int wm = (wid & 1) * 64;
    const int wn = (wid >> 1) * 32;

    float acc[4][4][4];
#pragma unroll
    for (int i = 0; i < 4; i++)
#pragma unroll
        for (int j = 0; j < 4; j++)
#pragma unroll
            for (int c = 0; c < 4; c++) acc[i][j][c] = 0.0f;

    const int aRow = (lane & 7) + ((lane >> 3) & 1) * 8;
    const int aCol = (lane >> 4) * 8;
    const int bRow = (lane & 7) + (lane >> 4) * 8;
    const int bCol = ((lane >> 3) & 1) * 8;

    const int lr = tid >> 1;
    const int lc = (tid & 1) * 2;

    const bf16* gA_h = Ah + (size_t)(m0 + lr) * K + lc * 8;
    const bf16* gA_l = Al + (size_t)(m0 + lr) * K + lc * 8;
    const bf16* gB_h = Bh + (size_t)(n0 + lr) * K + lc * 8;
    const bf16* gB_l = Bl + (size_t)(n0 + lr) * K + lc * 8;
    const uint32_t dRow = uS + lr * (GST * 2) + lc * 16;

#define ISSUE_STAGE(buf, k0)                                              \
    {                                                                     \
        uint32_t d = dRow + (buf) * STAGE_B;                              \
        cp16(d,              gA_h + (k0));                                \
        cp16(d + 16,         gA_h + (k0) + 8);                            \
        cp16(d + TILE_B,     gA_l + (k0));                                \
        cp16(d + TILE_B + 16,gA_l + (k0) + 8);                            \
        cp16(d + 2*TILE_B,      gB_h + (k0));                             \
        cp16(d + 2*TILE_B + 16, gB_h + (k0) + 8);                         \
        cp16(d + 3*TILE_B,      gB_l + (k0));                             \
        cp16(d + 3*TILE_B + 16, gB_l + (k0) + 8);                         \
    }

    const int niter = K / GBK;
    ISSUE_STAGE(0, 0)
    CP_COMMIT();

    for (int it = 0; it < niter; it++) {
        const int buf = it & 1;
        if (it + 1 < niter) {
            ISSUE_STAGE(buf ^ 1, (it + 1) * GBK)
            CP_COMMIT();
            CP_WAIT(1);
        } else {
            CP_WAIT(0);
        }
        __syncthreads();

        const uint32_t uAh = uS + buf * STAGE_B;
        const uint32_t uAl = uAh + TILE_B;
        const uint32_t uBh = uAh + 2 * TILE_B;
        const uint32_t uBl = uAh + 3 * TILE_B;

#pragma unroll
        for (int kk = 0; kk < GBK; kk += 16) {
            uint32_t ah[4][4], al[4][4], bh[4][2], bl[4][2];
#pragma unroll
            for (int mi = 0; mi < 4; mi++) {
                uint32_t off = (uint32_t)(((wm + mi * 16 + aRow) * GST + kk + aCol) * 2);
                ldmx4(ah[mi], uAh + off);
                ldmx4(al[mi], uAl + off);
            }
#pragma unroll
            for (int j = 0; j < 2; j++) {
                uint32_t off = (uint32_t)(((wn + j * 16 + bRow) * GST + kk + bCol) * 2);
                uint32_t rh[4], rl[4];
                ldmx4(rh, uBh + off);
                ldmx4(rl, uBl + off);
                bh[j * 2][0] = rh[0]; bh[j * 2][1] = rh[1];
                bh[j * 2 + 1][0] = rh[2]; bh[j * 2 + 1][1] = rh[3];
                bl[j * 2][0] = rl[0]; bl[j * 2][1] = rl[1];
                bl[j * 2 + 1][0] = rl[2]; bl[j * 2 + 1][1] = rl[3];
            }
#pragma unroll
            for (int mi = 0; mi < 4; mi++)
#pragma unroll
                for (int nj = 0; nj < 4; nj++) {
                    mma16816(acc[mi][nj], ah[mi], bh[nj]);
                    mma16816(acc[mi][nj], ah[mi], bl[nj]);
                    mma16816(acc[mi][nj], al[mi], bh[nj]);
                }
        }
        __syncthreads();
    }
#undef ISSUE_STAGE

    const int er = lane >> 2;
    const int ec = (lane & 3) * 2;
#pragma unroll
    for (int mi = 0; mi < 4; mi++)
#pragma unroll
        for (int nj = 0; nj < 4; nj++) {
            float v0 = acc[mi][nj][0], v1 = acc[mi][nj][1];
            float v2 = acc[mi][nj][2], v3 = acc[mi][nj][3];
            const int gm = m0 + wm + mi * 16 + er;
            const int n  = n0 + wn + nj * 8 + ec;
            if (mode == 1) {
                const int p = (n & 63) >> 1;
                const int t0 = gm & (T_ - 1);
                const int t1 = (gm + 8) & (T_ - 1);
                float c0 = cosb[t0 * 32 + p], s0 = sinb[t0 * 32 + p];
                float c1 = cosb[t1 * 32 + p], s1 = sinb[t1 * 32 + p];
                float e = v0, o = v1;
                v0 = e * c0 - o * s0; v1 = e * s0 + o * c0;
                e = v2; o = v3;
                v2 = e * c1 - o * s1; v3 = e * s1 + o * c1;
            }
            if (mode == 0) {
                float* p0 = C + (size_t)gm * N + n;
                *(float2*)p0           = make_float2(v0, v1);
                *(float2*)(p0 + 8 * N) = make_float2(v2, v3);
            } else {
                v0 *= outscale; v1 *= outscale; v2 *= outscale; v3 *= outscale;
                __nv_bfloat162 h0 = __floats2bfloat162_rn(v0, v1);
                float2 b0 = __bfloat1622float2(h0);
                __nv_bfloat162 lo0 = __floats2bfloat162_rn(v0 - b0.x, v1 - b0.y);
                __nv_bfloat162 h1 = __floats2bfloat162_rn(v2, v3);
                float2 b1 = __bfloat1622float2(h1);
                __nv_bfloat162 lo1 = __floats2bfloat162_rn(v2 - b1.x, v3 - b1.y);
                *(__nv_bfloat162*)(Ch + (size_t)gm * N + n) = h0;
                *(__nv_bfloat162*)(Cl + (size_t)gm * N + n) = lo0;
                *(__nv_bfloat162*)(Ch + (size_t)(gm + 8) * N + n) = h1;
                *(__nv_bfloat162*)(Cl + (size_t)(gm + 8) * N + n) = lo1;
            }
        }
}

// ---------------------------------------------------------------------------
// Causal GQA flash attention on HMMA, split-bf16 3-product for QK and PV.
// 4 warps / 64 queries per CTA. grid (T/64, B*NH).
// ---------------------------------------------------------------------------
#define NEG_BIG (-1e30f)
#define AST 72                     // smem row stride (bf16) for 64-col tiles
#define ATILE_B (64 * AST * 2)     // 9216 bytes
#define ATTN_SMEM (10 * ATILE_B)   // qh,ql + 2 stages x (kh,kl,vh,vl)

__global__ __launch_bounds__(128) void attn_hmma()
{
    const int qb = blockIdx.x;
    const int bh = blockIdx.y;
    const int b = bh >> 5, h = bh & 31;
    const int kvh = h >> 2;              // NH/NKV = 4

    extern __shared__ __align__(16) bf16 asm_[];
    const uint32_t uQ  = smem_u32(asm_);             // qh, ql tiles
    const uint32_t uKV = uQ + 2 * ATILE_B;           // [stage][kh,kl,vh,vl]

    const int tid  = threadIdx.x;
    const int wid  = tid >> 5;
    const int lane = tid & 31;

#define KVTILE(st, t) (uKV + (uint32_t)(((st) * 4 + (t)) * ATILE_B))

    // --- prologue: Q tiles + KV stage 0 ---
    {
        const size_t qrow = ((size_t)(b * T_) + qb * 64);
        for (int f = tid; f < 512; f += 128) {
            int r = f >> 3, c = f & 7;
            size_t off = (qrow + r) * (NH * HD) + h * HD + c * 8;
            uint32_t d = (uint32_t)((r * AST + c * 8) * 2);
            cp16(uQ + d, g_qh + off);
            cp16(uQ + ATILE_B + d, g_ql + off);
        }
    }
#define ISSUE_KV(st, kb)                                                    \
    {                                                                       \
        size_t rowb = ((size_t)(b * T_) + (size_t)(kb) * 64);               \
        for (int f = tid; f < 512; f += 128) {                              \
            int r = f >> 3, c = f & 7;                                      \
            size_t off = (rowb + r) * (NKV * HD) + kvh * HD + c * 8;        \
            uint32_t d = (uint32_t)((r * AST + c * 8) * 2);                 \
            cp16(KVTILE(st, 0) + d, g_kh + off);                            \
            cp16(KVTILE(st, 1) + d, g_kl + off);                            \
            cp16(KVTILE(st, 2) + d, g_vh + off);                            \
            cp16(KVTILE(st, 3) + d, g_vl + off);                            \
        }                                                                   \
    }
    ISSUE_KV(0, 0)
    CP_COMMIT();

    // lane addressing
    const int aRow = (lane & 7) + ((lane >> 3) & 1) * 8;   // A (Q) rows
    const int aCol = (lane >> 4) * 8;
    const int kRow = (lane & 7) + ((lane >> 4) & 1) * 8;   // K: bit4->n+8
    const int kCol = ((lane >> 3) & 1) * 8;                // bit3->k+8
    const int vRow = (lane & 7) + ((lane >> 3) & 1) * 8;   // V(trans): bit3->k+8
    const int vCol = ((lane >> 4) & 1) * 8;                // bit4->n+8

    uint32_t qh[4][4], ql[4][4];
    float o[8][4];
#pragma unroll
    for (int j = 0; j < 8; j++)
#pragma unroll
        for (int c = 0; c < 4; c++) o[j][c] = 0.0f;
    float m[2] = {NEG_BIG, NEG_BIG}, l[2] = {0.0f, 0.0f};

    const int r0 = lane >> 2;
    const int c0 = (lane & 3) * 2;

    for (int kb = 0; kb <= qb; kb++) {
        if (kb < qb) {
            ISSUE_KV((kb + 1) & 1, kb + 1)
            CP_COMMIT();
            CP_WAIT(1);
        } else {
            CP_WAIT(0);
        }
        __syncthreads();

        if (kb == 0) {
#pragma unroll
            for (int kk = 0; kk < 4; kk++) {
                uint32_t off = (uint32_t)(((wid * 16 + aRow) * AST + kk * 16 + aCol) * 2);
                ldmx4(qh[kk], uQ + off);
                ldmx4(ql[kk], uQ + ATILE_B + off);
            }
        }

        const uint32_t uKh = KVTILE(kb & 1, 0);
        const uint32_t uKl = KVTILE(kb & 1, 1);
        const uint32_t uVh = KVTILE(kb & 1, 2);
        const uint32_t uVl = KVTILE(kb & 1, 3);

        // --- scores ---
        float s[8][4];
#pragma unroll
        for (int j = 0; j < 8; j++)
#pragma unroll
            for (int c = 0; c < 4; c++) s[j][c] = 0.0f;

#pragma unroll
        for (int kk = 0; kk < 4; kk++) {
#pragma unroll
            for (int g = 0; g < 4; g++) {
                uint32_t off = (uint32_t)(((g * 16 + kRow) * AST + kk * 16 + kCol) * 2);
                uint32_t kf[4], lf[4];
                ldmx4(kf, uKh + off);
                ldmx4(lf, uKl + off);
                mma16816(s[2 * g],     qh[kk], kf);
                mma16816(s[2 * g],     ql[kk], kf);
                mma16816(s[2 * g],     qh[kk], lf);
                mma16816(s[2 * g + 1], qh[kk], kf + 2);
                mma16816(s[2 * g + 1], ql[kk], kf + 2);
                mma16816(s[2 * g + 1], qh[kk], lf + 2);
            }
        }

        // --- causal mask on the diagonal block ---
        if (kb == qb) {
            const int qr = wid * 16 + r0;
#pragma unroll
            for (int j = 0; j < 8; j++) {
                int col = j * 8 + c0;
                if (col     > qr)     s[j][0] = NEG_BIG;
                if (col + 1 > qr)     s[j][1] = NEG_BIG;
                if (col     > qr + 8) s[j][2] = NEG_BIG;
                if (col + 1 > qr + 8) s[j][3] = NEG_BIG;
            }
        }

        // --- online softmax (2 rows per thread) ---
#pragma unroll
        for (int hh = 0; hh < 2; hh++) {
            float rm = NEG_BIG;
#pragma unroll
            for (int j = 0; j < 8; j++)
                rm = fmaxf(rm, fmaxf(s[j][2 * hh], s[j][2 * hh + 1]));
            rm = fmaxf(rm, __shfl_xor_sync(0xffffffffu, rm, 1));
            rm = fmaxf(rm, __shfl_xor_sync(0xffffffffu, rm, 2));
            float mnew = fmaxf(m[hh], rm);
            float corr = __expf(m[hh] - mnew);
            float sum = 0.0f;
#pragma unroll
            for (int j = 0; j < 8; j++) {
                float p0 = __expf(s[j][2 * hh]     - mnew);
                float p1 = __expf(s[j][2 * hh + 1] - mnew);
                s[j][2 * hh] = p0; s[j][2 * hh + 1] = p1;
                sum += p0 + p1;
            }
            sum += __shfl_xor_sync(0xffffffffu, sum, 1);
            sum += __shfl_xor_sync(0xffffffffu, sum, 2);
            l[hh] = l[hh] * corr + sum;
            m[hh] = mnew;
#pragma unroll
            for (int j = 0; j < 8; j++) {
                o[j][2 * hh] *= corr; o[j][2 * hh + 1] *= corr;
            }
        }

        // --- PV: P (registers) x V (trans ldmatrix) ---
#pragma unroll
        for (int kk = 0; kk < 4; kk++) {
            uint32_t pha[4], pla[4];
#pragma unroll
            for (int t = 0; t < 2; t++) {
                int j = 2 * kk + t;
                __nv_bfloat162 hA = __floats2bfloat162_rn(s[j][0], s[j][1]);
                float2 bA = __bfloat1622float2(hA);
                __nv_bfloat162 lA = __floats2bfloat162_rn(s[j][0] - bA.x, s[j][1] - bA.y);
                __nv_bfloat162 hB = __floats2bfloat162_rn(s[j][2], s[j][3]);
                float2 bB = __bfloat1622float2(hB);
                __nv_bfloat162 lB = __floats2bfloat162_rn(s[j][2] - bB.x, s[j][3] - bB.y);
                pha[2 * t]     = *(uint32_t*)&hA;
                pha[2 * t + 1] = *(uint32_t*)&hB;
                pla[2 * t]     = *(uint32_t*)&lA;
                pla[2 * t + 1] = *(uint32_t*)&lB;
            }
#pragma unroll
            for (int g = 0; g < 4; g++) {
                uint32_t off = (uint32_t)(((kk * 16 + vRow) * AST + g * 16 + vCol) * 2);
                uint32_t vf[4], wf[4];
                ldmx4t(vf, uVh + off);
                ldmx4t(wf, uVl + off);
                mma16816(o[2 * g],     pha, vf);
                mma16816(o[2 * g],     pla, vf);
                mma16816(o[2 * g],     pha, wf);
                mma16816(o[2 * g + 1], pha, vf + 2);
                mma16816(o[2 * g + 1], pla, vf + 2);
                mma16816(o[2 * g + 1], pha, wf + 2);
            }
        }
        __syncthreads();
    }
#undef ISSUE_KV
#undef KVTILE

    // --- epilogue: normalize, split to bf16 hi/lo, write [token, NH*HD] ---
#pragma unroll
    for (int hh = 0; hh < 2; hh++) {
        float inv = 1.0f / l[hh];
        size_t tok = (size_t)(b * T_) + qb * 64 + wid * 16 + r0 + hh * 8;
#pragma unroll
        for (int j = 0; j < 8; j++) {
            float v0 = o[j][2 * hh] * inv;
            float v1 = o[j][2 * hh + 1] * inv;
            __nv_bfloat162 h2 = __floats2bfloat162_rn(v0, v1);
            float2 bk = __bfloat1622float2(h2);
            __nv_bfloat162 l2 = __floats2bfloat162_rn(v0 - bk.x, v1 - bk.y);
            size_t off = tok * (NH * HD) + h * HD + j * 8 + c0;
            *(__nv_bfloat162*)(g_oh + off) = h2;
            *(__nv_bfloat162*)(g_ol + off) = l2;
        }
    }
}

// ---------------------------------------------------------------------------
// Launch
// ---------------------------------------------------------------------------
extern "C" void kernel_launch(void* const* d_in, const int* in_sizes, int n_in,
                              void* d_out, int out_size)
{
    const float* x    = (const float*)d_in[0];
    const float* cosb = (const float*)d_in[1];
    const float* sinb = (const float*)d_in[2];
    const float* Wq   = (const float*)d_in[3];
    const float* Wk   = (const float*)d_in[4];
    const float* Wv   = (const float*)d_in[5];
    const float* Wo   = (const float*)d_in[6];
    float* out = (float*)d_out;

    bf16 *xh, *xl, *wqh, *wql, *wkh, *wkl, *wvh, *wvl, *woh, *wol;
    bf16 *qh, *ql, *kh, *kl, *vh, *vl, *oh, *ol;
    cudaGetSymbolAddress((void**)&xh, g_xh);   cudaGetSymbolAddress((void**)&xl, g_xl);
    cudaGetSymbolAddress((void**)&wqh, g_wqh); cudaGetSymbolAddress((void**)&wql, g_wql);
    cudaGetSymbolAddress((void**)&wkh, g_wkh); cudaGetSymbolAddress((void**)&wkl, g_wkl);
    cudaGetSymbolAddress((void**)&wvh, g_wvh); cudaGetSymbolAddress((void**)&wvl, g_wvl);
    cudaGetSymbolAddress((void**)&woh, g_woh); cudaGetSymbolAddress((void**)&wol, g_wol);
    cudaGetSymbolAddress((void**)&qh, g_qh);   cudaGetSymbolAddress((void**)&ql, g_ql);
    cudaGetSymbolAddress((void**)&kh, g_kh);   cudaGetSymbolAddress((void**)&kl, g_kl);
    cudaGetSymbolAddress((void**)&vh, g_vh);   cudaGetSymbolAddress((void**)&vl, g_vl);
    cudaGetSymbolAddress((void**)&oh, g_oh);   cudaGetSymbolAddress((void**)&ol, g_ol);

    cudaFuncSetAttribute(gemm_hmma3, cudaFuncAttributeMaxDynamicSharedMemorySize,
                         GEMM_SMEM);
    cudaFuncSetAttribute(attn_hmma, cudaFuncAttributeMaxDynamicSharedMemorySize,
                         ATTN_SMEM);

    const int M = B_ * T_;  // 4096

    // Splits (x + weights)
    {
        int n4;
        n4 = M * DIM_ / 4;
        split_kernel<<<(n4 + 255) / 256, 256>>>((const float4*)x, (uint2*)xh, (uint2*)xl, n4);
        n4 = NH * HD * DIM_ / 4;
        split_kernel<<<(n4 + 255) / 256, 256>>>((const float4*)Wq, (uint2*)wqh, (uint2*)wql, n4);
        n4 = NKV * HD * DIM_ / 4;
        split_kernel<<<(n4 + 255) / 256, 256>>>((const float4*)Wk, (uint2*)wkh, (uint2*)wkl, n4);
        split_kernel<<<(n4 + 255) / 256, 256>>>((const float4*)Wv, (uint2*)wvh, (uint2*)wvl, n4);
        n4 = DIM_ * NH * HD / 4;
        split_kernel<<<(n4 + 255) / 256, 256>>>((const float4*)Wo, (uint2*)woh, (uint2*)wol, n4);
    }

    // QKV projections. Q: RoPE + 1/sqrt(d) + split. K: RoPE + split. V: split.
    gemm_hmma3<<<dim3((NH * HD) / 128, M / 128), 256, GEMM_SMEM>>>(
        xh, xl, wqh, wql, nullptr, qh, ql, M, NH * HD, DIM_, cosb, sinb, 1, 0.125f);
    gemm_hmma3<<<dim3((NKV * HD) / 128, M / 128), 256, GEMM_SMEM>>>(
        xh, xl, wkh, wkl, nullptr, kh, kl, M, NKV * HD, DIM_, cosb, sinb, 1, 1.0f);
    gemm_hmma3<<<dim3((NKV * HD) / 128, M / 128), 256, GEMM_SMEM>>>(
        xh, xl, wvh, wvl, nullptr, vh, vl, M, NKV * HD, DIM_, cosb, sinb, 2, 1.0f);

    // Attention (HMMA), writes split bf16 output
    attn_hmma<<<dim3(T_ / 64, B_ * NH), 128, ATTN_SMEM>>>();

    // Output projection -> fp32 d_out
    gemm_hmma3<<<dim3(DIM_ / 128, M / 128), 256, GEMM_SMEM>>>(
        oh, ol, woh, wol, out, nullptr, nullptr, M, DIM_, DIM_, cosb, sinb, 0, 1.0f);
}